// round 4
// baseline (speedup 1.0000x reference)
#include <cuda_runtime.h>
#include <math.h>
#include <stdint.h>

#define TSEQ    2048
#define DMODEL  512
#define NHEADS  8
#define DH      64
#define MAXB    4
#define NEG_INF_F (-1.0e9f)
#define ATT_SCALE 0.125f   /* 1/sqrt(64) */

// Scratch (device globals: allocation-free per harness rules)
__device__ float g_Q[(size_t)MAXB * NHEADS * TSEQ * DH];   // (B,H,T,dh)
__device__ float g_K[(size_t)MAXB * NHEADS * TSEQ * DH];
__device__ float g_V[(size_t)MAXB * NHEADS * TSEQ * DH];
__device__ float g_AO[(size_t)MAXB * TSEQ * DMODEL];       // (B*T, D) row-major

// ---------------------------------------------------------------------------
// GEMM: C = A @ W^T.  A: (M,512) row-major, W: (512,512) row-major.
// LAYOUT 0: C row-major (M,512).  LAYOUT 1: C in (B,H,T,dh) layout.
// Tile 128x64, k-tile 16, 256 threads, 8x4 micro-tile.
// ---------------------------------------------------------------------------
#define BM 128
#define BN 64
#define BK 16

template <int LAYOUT>
__global__ __launch_bounds__(256) void gemm_kernel(
    const float* __restrict__ A, const float* __restrict__ W,
    float* __restrict__ C, int M)
{
    __shared__ float As[BK][BM + 4];   // transposed A tile (k-major)
    __shared__ float Ws[BK][BN + 4];   // transposed W tile

    const int tid = threadIdx.x;
    const int tx = tid & 15;
    const int ty = tid >> 4;
    const int m0 = blockIdx.y * BM;
    const int n0 = blockIdx.x * BN;

    float acc[8][4];
#pragma unroll
    for (int i = 0; i < 8; i++)
#pragma unroll
        for (int j = 0; j < 4; j++) acc[i][j] = 0.0f;

    const int arow = tid >> 2;        // 0..63
    const int akq  = (tid & 3) * 4;   // 0,4,8,12

    for (int kt = 0; kt < DMODEL; kt += BK) {
        // Load A tile (128x16), transpose to As[k][m]
#pragma unroll
        for (int half = 0; half < 2; half++) {
            int r = arow + half * 64;
            float4 v = *(const float4*)(A + (size_t)(m0 + r) * DMODEL + kt + akq);
            As[akq + 0][r] = v.x;
            As[akq + 1][r] = v.y;
            As[akq + 2][r] = v.z;
            As[akq + 3][r] = v.w;
        }
        // Load W tile (64x16), transpose to Ws[k][n]
        {
            float4 v = *(const float4*)(W + (size_t)(n0 + arow) * DMODEL + kt + akq);
            Ws[akq + 0][arow] = v.x;
            Ws[akq + 1][arow] = v.y;
            Ws[akq + 2][arow] = v.z;
            Ws[akq + 3][arow] = v.w;
        }
        __syncthreads();

#pragma unroll
        for (int kk = 0; kk < BK; kk++) {
            float a[8], bv[4];
            float4 a0 = *(const float4*)&As[kk][ty * 8];
            float4 a1 = *(const float4*)&As[kk][ty * 8 + 4];
            a[0] = a0.x; a[1] = a0.y; a[2] = a0.z; a[3] = a0.w;
            a[4] = a1.x; a[5] = a1.y; a[6] = a1.z; a[7] = a1.w;
            float4 bb = *(const float4*)&Ws[kk][tx * 4];
            bv[0] = bb.x; bv[1] = bb.y; bv[2] = bb.z; bv[3] = bb.w;
#pragma unroll
            for (int i = 0; i < 8; i++)
#pragma unroll
                for (int j = 0; j < 4; j++)
                    acc[i][j] += a[i] * bv[j];
        }
        __syncthreads();
    }

#pragma unroll
    for (int i = 0; i < 8; i++) {
        int m = m0 + ty * 8 + i;
#pragma unroll
        for (int j = 0; j < 4; j++) {
            int n = n0 + tx * 4 + j;
            if (LAYOUT == 0) {
                C[(size_t)m * DMODEL + n] = acc[i][j];
            } else {
                // (B,H,T,dh): b = m>>11, t = m&2047, h = n>>6, d = n&63
                size_t idx = ((((size_t)(m >> 11) * NHEADS + (n >> 6)) * TSEQ
                               + (size_t)(m & (TSEQ - 1))) * DH) + (n & (DH - 1));
                C[idx] = acc[i][j];
            }
        }
    }
}

// ---------------------------------------------------------------------------
// Banded FlashAttention with adaptive-span soft mask.
// One block per (b*H+h, q-tile of 64). 256 threads (16x16), 4x4 micro-tiles.
// Online softmax; key loop restricted to the span window.
// ---------------------------------------------------------------------------
#define SROW 65                     // padded row stride (floats)
#define ATT_SMEM (4 * 64 * SROW * 4)

__global__ __launch_bounds__(256) void attn_kernel(const float* __restrict__ spans)
{
    extern __shared__ float sm[];
    float* Qs = sm;                   // [64][65]
    float* Ks = sm + 64 * SROW;
    float* Vs = sm + 2 * 64 * SROW;
    float* Ps = sm + 3 * 64 * SROW;

    const int tid = threadIdx.x;
    const int tx = tid & 15;
    const int ty = tid >> 4;
    const int bh = blockIdx.y;          // b*H + h
    const int h  = bh & (NHEADS - 1);
    const int b  = bh >> 3;
    const int qt = blockIdx.x;
    const int q0 = qt << 6;

    const float sp  = fminf(fmaxf(spans[h], 0.0f), 1.0f);
    const float eff = sp * 512.0f;
    const int dist_max = (int)floorf(eff) + 1;
    const int kt0 = max(0, q0 - dist_max) >> 6;

    const float* Qg = g_Q + ((size_t)bh * TSEQ + q0) * DH;
    const float* Kg = g_K + (size_t)bh * TSEQ * DH;
    const float* Vg = g_V + (size_t)bh * TSEQ * DH;

    // Load Q tile (contiguous 4096 floats)
#pragma unroll
    for (int it = 0; it < 4; it++) {
        int f = tid + it * 256;
        int r = f >> 4, dq = (f & 15) << 2;
        float4 v = ((const float4*)Qg)[f];
        Qs[r * SROW + dq + 0] = v.x;
        Qs[r * SROW + dq + 1] = v.y;
        Qs[r * SROW + dq + 2] = v.z;
        Qs[r * SROW + dq + 3] = v.w;
    }

    float mrow[4], lrow[4], o[4][4];
#pragma unroll
    for (int i = 0; i < 4; i++) {
        mrow[i] = -1e30f;
        lrow[i] = 0.0f;
#pragma unroll
        for (int j = 0; j < 4; j++) o[i][j] = 0.0f;
    }

    for (int kt = kt0; kt <= qt; kt++) {
        __syncthreads();   // previous O-loop done reading Ks/Vs/Ps
        const float4* K4 = (const float4*)(Kg + ((size_t)kt << 6) * DH);
        const float4* V4 = (const float4*)(Vg + ((size_t)kt << 6) * DH);
#pragma unroll
        for (int it = 0; it < 4; it++) {
            int f = tid + it * 256;
            int r = f >> 4, dq = (f & 15) << 2;
            float4 kv = K4[f];
            Ks[r * SROW + dq + 0] = kv.x;
            Ks[r * SROW + dq + 1] = kv.y;
            Ks[r * SROW + dq + 2] = kv.z;
            Ks[r * SROW + dq + 3] = kv.w;
            float4 vv = V4[f];
            Vs[r * SROW + dq + 0] = vv.x;
            Vs[r * SROW + dq + 1] = vv.y;
            Vs[r * SROW + dq + 2] = vv.z;
            Vs[r * SROW + dq + 3] = vv.w;
        }
        __syncthreads();

        // S = Q K^T (64x64 tile, each thread 4x4)
        float s[4][4];
#pragma unroll
        for (int i = 0; i < 4; i++)
#pragma unroll
            for (int j = 0; j < 4; j++) s[i][j] = 0.0f;

#pragma unroll 8
        for (int d = 0; d < 64; d++) {
            float qv[4], kv[4];
#pragma unroll
            for (int i = 0; i < 4; i++) qv[i] = Qs[(ty * 4 + i) * SROW + d];
#pragma unroll
            for (int j = 0; j < 4; j++) kv[j] = Ks[(tx * 4 + j) * SROW + d];
#pragma unroll
            for (int i = 0; i < 4; i++)
#pragma unroll
                for (int j = 0; j < 4; j++)
                    s[i][j] += qv[i] * kv[j];
        }

        // scale + adaptive-span mask + row max
        float mx[4];
#pragma unroll
        for (int i = 0; i < 4; i++) {
            float qgf = (float)(q0 + ty * 4 + i);
            float rowm = -1e30f;
#pragma unroll
            for (int j = 0; j < 4; j++) {
                float jjf = (float)((kt << 6) + tx * 4 + j);
                float dist = qgf - jjf;
                float R = (eff - dist + 1.0f) * 0.25f;
                float val;
                if (dist < 0.0f || R <= 0.0f)      val = NEG_INF_F;
                else if (R >= 1.0f)                val = 0.0f;   // log(1+1e-10) == 0 in fp32
                else                               val = __logf(R + 1e-10f);
                s[i][j] = s[i][j] * ATT_SCALE + val;
                rowm = fmaxf(rowm, s[i][j]);
            }
            rowm = fmaxf(rowm, __shfl_xor_sync(0xffffffffu, rowm, 1));
            rowm = fmaxf(rowm, __shfl_xor_sync(0xffffffffu, rowm, 2));
            rowm = fmaxf(rowm, __shfl_xor_sync(0xffffffffu, rowm, 4));
            rowm = fmaxf(rowm, __shfl_xor_sync(0xffffffffu, rowm, 8));
            mx[i] = rowm;
        }

        // online softmax update; stage P in shared
#pragma unroll
        for (int i = 0; i < 4; i++) {
            float mn = fmaxf(mrow[i], mx[i]);
            float corr = __expf(mrow[i] - mn);
            mrow[i] = mn;
            float rs = 0.0f;
#pragma unroll
            for (int j = 0; j < 4; j++) {
                float p = __expf(s[i][j] - mn);
                rs += p;
                Ps[(ty * 4 + i) * SROW + tx * 4 + j] = p;
            }
            rs += __shfl_xor_sync(0xffffffffu, rs, 1);
            rs += __shfl_xor_sync(0xffffffffu, rs, 2);
            rs += __shfl_xor_sync(0xffffffffu, rs, 4);
            rs += __shfl_xor_sync(0xffffffffu, rs, 8);
            lrow[i] = lrow[i] * corr + rs;
#pragma unroll
            for (int j = 0; j < 4; j++) o[i][j] *= corr;
        }
        __syncthreads();

        // O += P @ V
#pragma unroll 8
        for (int c = 0; c < 64; c++) {
            float pv[4], vv[4];
#pragma unroll
            for (int i = 0; i < 4; i++) pv[i] = Ps[(ty * 4 + i) * SROW + c];
#pragma unroll
            for (int j = 0; j < 4; j++) vv[j] = Vs[c * SROW + tx * 4 + j];
#pragma unroll
            for (int i = 0; i < 4; i++)
#pragma unroll
                for (int j = 0; j < 4; j++)
                    o[i][j] += pv[i] * vv[j];
        }
    }

    // normalize + write to (B*T, D) layout for the output projection
#pragma unroll
    for (int i = 0; i < 4; i++) {
        float inv = 1.0f / lrow[i];
        int q = q0 + ty * 4 + i;
        size_t base = ((size_t)(b * TSEQ + q)) * DMODEL + h * DH + tx * 4;
#pragma unroll
        for (int j = 0; j < 4; j++)
            g_AO[base + j] = o[i][j] * inv;
    }
}

// ---------------------------------------------------------------------------
__global__ void span_loss_kernel(const float* __restrict__ spans,
                                 float* __restrict__ out, int off)
{
    if (threadIdx.x == 0) {
        float sum = 0.0f;
        for (int i = 0; i < NHEADS; i++)
            sum += fminf(fmaxf(spans[i], 0.0f), 1.0f);
        out[off] = 2e-4f * (sum / (float)NHEADS);
    }
}

// ---------------------------------------------------------------------------
extern "C" void kernel_launch(void* const* d_in, const int* in_sizes, int n_in,
                              void* d_out, int out_size)
{
    const float* x  = (const float*)d_in[0];
    const float* wq = (const float*)d_in[1];
    const float* wk = (const float*)d_in[2];
    const float* wv = (const float*)d_in[3];
    const float* wo = (const float*)d_in[4];
    const float* sp = (const float*)d_in[5];

    const int M = in_sizes[0] / DMODEL;   // B*T
    const int B = M / TSEQ;

    float *pQ, *pK, *pV, *pAO;
    cudaGetSymbolAddress((void**)&pQ,  g_Q);
    cudaGetSymbolAddress((void**)&pK,  g_K);
    cudaGetSymbolAddress((void**)&pV,  g_V);
    cudaGetSymbolAddress((void**)&pAO, g_AO);

    dim3 gg(DMODEL / BN, M / BM);
    gemm_kernel<1><<<gg, 256>>>(x, wq, pQ, M);
    gemm_kernel<1><<<gg, 256>>>(x, wk, pK, M);
    gemm_kernel<1><<<gg, 256>>>(x, wv, pV, M);

    cudaFuncSetAttribute(attn_kernel,
                         cudaFuncAttributeMaxDynamicSharedMemorySize, ATT_SMEM);
    attn_kernel<<<dim3(TSEQ / 64, B * NHEADS), 256, ATT_SMEM>>>(sp);

    gemm_kernel<0><<<gg, 256>>>(pAO, wo, (float*)d_out, M);

    if (out_size > M * DMODEL)
        span_loss_kernel<<<1, 32>>>(sp, (float*)d_out, M * DMODEL);
}

// round 5
// speedup vs baseline: 1.0004x; 1.0004x over previous
#include <cuda_runtime.h>
#include <math.h>
#include <stdint.h>

#define TSEQ    2048
#define DMODEL  512
#define NHEADS  8
#define DH      64
#define MAXB    4
#define NEG_INF_F (-1.0e9f)
#define ATT_SCALE 0.125f   /* 1/sqrt(64) */

// Scratch (device globals: allocation-free per harness rules)
__device__ float g_Q[(size_t)MAXB * NHEADS * TSEQ * DH];   // (B,H,T,dh)
__device__ float g_K[(size_t)MAXB * NHEADS * TSEQ * DH];
__device__ float g_V[(size_t)MAXB * NHEADS * TSEQ * DH];
__device__ float g_AO[(size_t)MAXB * TSEQ * DMODEL];       // (B*T, D) row-major

// ---------------------------------------------------------------------------
// GEMM: C = A @ W^T.  A: (M,512) row-major, W: (512,512) row-major.
// LAYOUT 0: C row-major (M,512).  LAYOUT 1: C in (B,H,T,dh) layout.
// Tile 128x64, k-tile 16, 256 threads, 8x4 micro-tile.
// ---------------------------------------------------------------------------
#define BM 128
#define BN 64
#define BK 16

template <int LAYOUT>
__global__ __launch_bounds__(256) void gemm_kernel(
    const float* __restrict__ A, const float* __restrict__ W,
    float* __restrict__ C, int M)
{
    __shared__ float As[BK][BM + 4];   // transposed A tile (k-major)
    __shared__ float Ws[BK][BN + 4];   // transposed W tile

    const int tid = threadIdx.x;
    const int tx = tid & 15;
    const int ty = tid >> 4;
    const int m0 = blockIdx.y * BM;
    const int n0 = blockIdx.x * BN;

    float acc[8][4];
#pragma unroll
    for (int i = 0; i < 8; i++)
#pragma unroll
        for (int j = 0; j < 4; j++) acc[i][j] = 0.0f;

    const int arow = tid >> 2;        // 0..63
    const int akq  = (tid & 3) * 4;   // 0,4,8,12

    for (int kt = 0; kt < DMODEL; kt += BK) {
        // Load A tile (128x16), transpose to As[k][m]
#pragma unroll
        for (int half = 0; half < 2; half++) {
            int r = arow + half * 64;
            float4 v = *(const float4*)(A + (size_t)(m0 + r) * DMODEL + kt + akq);
            As[akq + 0][r] = v.x;
            As[akq + 1][r] = v.y;
            As[akq + 2][r] = v.z;
            As[akq + 3][r] = v.w;
        }
        // Load W tile (64x16), transpose to Ws[k][n]
        {
            float4 v = *(const float4*)(W + (size_t)(n0 + arow) * DMODEL + kt + akq);
            Ws[akq + 0][arow] = v.x;
            Ws[akq + 1][arow] = v.y;
            Ws[akq + 2][arow] = v.z;
            Ws[akq + 3][arow] = v.w;
        }
        __syncthreads();

#pragma unroll
        for (int kk = 0; kk < BK; kk++) {
            float a[8], bv[4];
            float4 a0 = *(const float4*)&As[kk][ty * 8];
            float4 a1 = *(const float4*)&As[kk][ty * 8 + 4];
            a[0] = a0.x; a[1] = a0.y; a[2] = a0.z; a[3] = a0.w;
            a[4] = a1.x; a[5] = a1.y; a[6] = a1.z; a[7] = a1.w;
            float4 bb = *(const float4*)&Ws[kk][tx * 4];
            bv[0] = bb.x; bv[1] = bb.y; bv[2] = bb.z; bv[3] = bb.w;
#pragma unroll
            for (int i = 0; i < 8; i++)
#pragma unroll
                for (int j = 0; j < 4; j++)
                    acc[i][j] += a[i] * bv[j];
        }
        __syncthreads();
    }

#pragma unroll
    for (int i = 0; i < 8; i++) {
        int m = m0 + ty * 8 + i;
#pragma unroll
        for (int j = 0; j < 4; j++) {
            int n = n0 + tx * 4 + j;
            if (LAYOUT == 0) {
                C[(size_t)m * DMODEL + n] = acc[i][j];
            } else {
                // (B,H,T,dh): b = m>>11, t = m&2047, h = n>>6, d = n&63
                size_t idx = ((((size_t)(m >> 11) * NHEADS + (n >> 6)) * TSEQ
                               + (size_t)(m & (TSEQ - 1))) * DH) + (n & (DH - 1));
                C[idx] = acc[i][j];
            }
        }
    }
}

// ---------------------------------------------------------------------------
// Banded FlashAttention with adaptive-span soft mask.
// One block per (b*H+h, q-tile of 64). 256 threads (16x16), 4x4 micro-tiles.
// Online softmax; key loop restricted to the span window.
// ---------------------------------------------------------------------------
#define SROW 65                     // padded row stride (floats)
#define ATT_SMEM (4 * 64 * SROW * 4)

__global__ __launch_bounds__(256) void attn_kernel(const float* __restrict__ spans)
{
    extern __shared__ float sm[];
    float* Qs = sm;                   // [64][65]
    float* Ks = sm + 64 * SROW;
    float* Vs = sm + 2 * 64 * SROW;
    float* Ps = sm + 3 * 64 * SROW;

    const int tid = threadIdx.x;
    const int tx = tid & 15;
    const int ty = tid >> 4;
    const int bh = blockIdx.y;          // b*H + h
    const int h  = bh & (NHEADS - 1);
    const int b  = bh >> 3;
    const int qt = blockIdx.x;
    const int q0 = qt << 6;

    const float sp  = fminf(fmaxf(spans[h], 0.0f), 1.0f);
    const float eff = sp * 512.0f;
    const int dist_max = (int)floorf(eff) + 1;
    const int kt0 = max(0, q0 - dist_max) >> 6;

    const float* Qg = g_Q + ((size_t)bh * TSEQ + q0) * DH;
    const float* Kg = g_K + (size_t)bh * TSEQ * DH;
    const float* Vg = g_V + (size_t)bh * TSEQ * DH;

    // Load Q tile (contiguous 4096 floats)
#pragma unroll
    for (int it = 0; it < 4; it++) {
        int f = tid + it * 256;
        int r = f >> 4, dq = (f & 15) << 2;
        float4 v = ((const float4*)Qg)[f];
        Qs[r * SROW + dq + 0] = v.x;
        Qs[r * SROW + dq + 1] = v.y;
        Qs[r * SROW + dq + 2] = v.z;
        Qs[r * SROW + dq + 3] = v.w;
    }

    float mrow[4], lrow[4], o[4][4];
#pragma unroll
    for (int i = 0; i < 4; i++) {
        mrow[i] = -1e30f;
        lrow[i] = 0.0f;
#pragma unroll
        for (int j = 0; j < 4; j++) o[i][j] = 0.0f;
    }

    for (int kt = kt0; kt <= qt; kt++) {
        __syncthreads();   // previous O-loop done reading Ks/Vs/Ps
        const float4* K4 = (const float4*)(Kg + ((size_t)kt << 6) * DH);
        const float4* V4 = (const float4*)(Vg + ((size_t)kt << 6) * DH);
#pragma unroll
        for (int it = 0; it < 4; it++) {
            int f = tid + it * 256;
            int r = f >> 4, dq = (f & 15) << 2;
            float4 kv = K4[f];
            Ks[r * SROW + dq + 0] = kv.x;
            Ks[r * SROW + dq + 1] = kv.y;
            Ks[r * SROW + dq + 2] = kv.z;
            Ks[r * SROW + dq + 3] = kv.w;
            float4 vv = V4[f];
            Vs[r * SROW + dq + 0] = vv.x;
            Vs[r * SROW + dq + 1] = vv.y;
            Vs[r * SROW + dq + 2] = vv.z;
            Vs[r * SROW + dq + 3] = vv.w;
        }
        __syncthreads();

        // S = Q K^T (64x64 tile, each thread 4x4)
        float s[4][4];
#pragma unroll
        for (int i = 0; i < 4; i++)
#pragma unroll
            for (int j = 0; j < 4; j++) s[i][j] = 0.0f;

#pragma unroll 8
        for (int d = 0; d < 64; d++) {
            float qv[4], kv[4];
#pragma unroll
            for (int i = 0; i < 4; i++) qv[i] = Qs[(ty * 4 + i) * SROW + d];
#pragma unroll
            for (int j = 0; j < 4; j++) kv[j] = Ks[(tx * 4 + j) * SROW + d];
#pragma unroll
            for (int i = 0; i < 4; i++)
#pragma unroll
                for (int j = 0; j < 4; j++)
                    s[i][j] += qv[i] * kv[j];
        }

        // scale + adaptive-span mask + row max
        float mx[4];
#pragma unroll
        for (int i = 0; i < 4; i++) {
            float qgf = (float)(q0 + ty * 4 + i);
            float rowm = -1e30f;
#pragma unroll
            for (int j = 0; j < 4; j++) {
                float jjf = (float)((kt << 6) + tx * 4 + j);
                float dist = qgf - jjf;
                float R = (eff - dist + 1.0f) * 0.25f;
                float val;
                if (dist < 0.0f || R <= 0.0f)      val = NEG_INF_F;
                else if (R >= 1.0f)                val = 0.0f;   // log(1+1e-10) == 0 in fp32
                else                               val = __logf(R + 1e-10f);
                s[i][j] = s[i][j] * ATT_SCALE + val;
                rowm = fmaxf(rowm, s[i][j]);
            }
            rowm = fmaxf(rowm, __shfl_xor_sync(0xffffffffu, rowm, 1));
            rowm = fmaxf(rowm, __shfl_xor_sync(0xffffffffu, rowm, 2));
            rowm = fmaxf(rowm, __shfl_xor_sync(0xffffffffu, rowm, 4));
            rowm = fmaxf(rowm, __shfl_xor_sync(0xffffffffu, rowm, 8));
            mx[i] = rowm;
        }

        // online softmax update; stage P in shared
#pragma unroll
        for (int i = 0; i < 4; i++) {
            float mn = fmaxf(mrow[i], mx[i]);
            float corr = __expf(mrow[i] - mn);
            mrow[i] = mn;
            float rs = 0.0f;
#pragma unroll
            for (int j = 0; j < 4; j++) {
                float p = __expf(s[i][j] - mn);
                rs += p;
                Ps[(ty * 4 + i) * SROW + tx * 4 + j] = p;
            }
            rs += __shfl_xor_sync(0xffffffffu, rs, 1);
            rs += __shfl_xor_sync(0xffffffffu, rs, 2);
            rs += __shfl_xor_sync(0xffffffffu, rs, 4);
            rs += __shfl_xor_sync(0xffffffffu, rs, 8);
            lrow[i] = lrow[i] * corr + rs;
#pragma unroll
            for (int j = 0; j < 4; j++) o[i][j] *= corr;
        }
        __syncthreads();

        // O += P @ V
#pragma unroll 8
        for (int c = 0; c < 64; c++) {
            float pv[4], vv[4];
#pragma unroll
            for (int i = 0; i < 4; i++) pv[i] = Ps[(ty * 4 + i) * SROW + c];
#pragma unroll
            for (int j = 0; j < 4; j++) vv[j] = Vs[c * SROW + tx * 4 + j];
#pragma unroll
            for (int i = 0; i < 4; i++)
#pragma unroll
                for (int j = 0; j < 4; j++)
                    o[i][j] += pv[i] * vv[j];
        }
    }

    // normalize + write to (B*T, D) layout for the output projection
#pragma unroll
    for (int i = 0; i < 4; i++) {
        float inv = 1.0f / lrow[i];
        int q = q0 + ty * 4 + i;
        size_t base = ((size_t)(b * TSEQ + q)) * DMODEL + h * DH + tx * 4;
#pragma unroll
        for (int j = 0; j < 4; j++)
            g_AO[base + j] = o[i][j] * inv;
    }
}

// ---------------------------------------------------------------------------
__global__ void span_loss_kernel(const float* __restrict__ spans,
                                 float* __restrict__ out, int off)
{
    if (threadIdx.x == 0) {
        float sum = 0.0f;
        for (int i = 0; i < NHEADS; i++)
            sum += fminf(fmaxf(spans[i], 0.0f), 1.0f);
        out[off] = 2e-4f * (sum / (float)NHEADS);
    }
}

// ---------------------------------------------------------------------------
extern "C" void kernel_launch(void* const* d_in, const int* in_sizes, int n_in,
                              void* d_out, int out_size)
{
    const float* x  = (const float*)d_in[0];
    const float* wq = (const float*)d_in[1];
    const float* wk = (const float*)d_in[2];
    const float* wv = (const float*)d_in[3];
    const float* wo = (const float*)d_in[4];
    const float* sp = (const float*)d_in[5];

    const int M = in_sizes[0] / DMODEL;   // B*T
    const int B = M / TSEQ;

    float *pQ, *pK, *pV, *pAO;
    cudaGetSymbolAddress((void**)&pQ,  g_Q);
    cudaGetSymbolAddress((void**)&pK,  g_K);
    cudaGetSymbolAddress((void**)&pV,  g_V);
    cudaGetSymbolAddress((void**)&pAO, g_AO);

    dim3 gg(DMODEL / BN, M / BM);
    gemm_kernel<1><<<gg, 256>>>(x, wq, pQ, M);
    gemm_kernel<1><<<gg, 256>>>(x, wk, pK, M);
    gemm_kernel<1><<<gg, 256>>>(x, wv, pV, M);

    cudaFuncSetAttribute(attn_kernel,
                         cudaFuncAttributeMaxDynamicSharedMemorySize, ATT_SMEM);
    attn_kernel<<<dim3(TSEQ / 64, B * NHEADS), 256, ATT_SMEM>>>(sp);

    gemm_kernel<0><<<gg, 256>>>(pAO, wo, (float*)d_out, M);

    if (out_size > M * DMODEL)
        span_loss_kernel<<<1, 32>>>(sp, (float*)d_out, M * DMODEL);
}

// round 6
// speedup vs baseline: 1.0051x; 1.0047x over previous
#include <cuda_runtime.h>
#include <math.h>
#include <stdint.h>

#define TSEQ    2048
#define DMODEL  512
#define NHEADS  8
#define DH      64
#define MAXB    4
#define NEG_INF_F (-1.0e9f)
#define ATT_SCALE 0.125f   /* 1/sqrt(64) */

// Scratch (device globals: allocation-free per harness rules)
__device__ float g_Q[(size_t)MAXB * NHEADS * TSEQ * DH];   // (B,H,T,dh)
__device__ float g_K[(size_t)MAXB * NHEADS * TSEQ * DH];
__device__ float g_V[(size_t)MAXB * NHEADS * TSEQ * DH];
__device__ float g_AO[(size_t)MAXB * TSEQ * DMODEL];       // (B*T, D) row-major

// ---------------------------------------------------------------------------
// GEMM: C = A @ W^T.  A: (M,512) row-major, W: (512,512) row-major.
// LAYOUT 0: C row-major (M,512).  LAYOUT 1: C in (B,H,T,dh) layout.
// Tile 128x64, k-tile 16, 256 threads, 8x4 micro-tile.
// ---------------------------------------------------------------------------
#define BM 128
#define BN 64
#define BK 16

template <int LAYOUT>
__global__ __launch_bounds__(256) void gemm_kernel(
    const float* __restrict__ A, const float* __restrict__ W,
    float* __restrict__ C, int M)
{
    __shared__ float As[BK][BM + 4];   // transposed A tile (k-major)
    __shared__ float Ws[BK][BN + 4];   // transposed W tile

    const int tid = threadIdx.x;
    const int tx = tid & 15;
    const int ty = tid >> 4;
    const int m0 = blockIdx.y * BM;
    const int n0 = blockIdx.x * BN;

    float acc[8][4];
#pragma unroll
    for (int i = 0; i < 8; i++)
#pragma unroll
        for (int j = 0; j < 4; j++) acc[i][j] = 0.0f;

    const int arow = tid >> 2;        // 0..63
    const int akq  = (tid & 3) * 4;   // 0,4,8,12

    for (int kt = 0; kt < DMODEL; kt += BK) {
        // Load A tile (128x16), transpose to As[k][m]
#pragma unroll
        for (int half = 0; half < 2; half++) {
            int r = arow + half * 64;
            float4 v = *(const float4*)(A + (size_t)(m0 + r) * DMODEL + kt + akq);
            As[akq + 0][r] = v.x;
            As[akq + 1][r] = v.y;
            As[akq + 2][r] = v.z;
            As[akq + 3][r] = v.w;
        }
        // Load W tile (64x16), transpose to Ws[k][n]
        {
            float4 v = *(const float4*)(W + (size_t)(n0 + arow) * DMODEL + kt + akq);
            Ws[akq + 0][arow] = v.x;
            Ws[akq + 1][arow] = v.y;
            Ws[akq + 2][arow] = v.z;
            Ws[akq + 3][arow] = v.w;
        }
        __syncthreads();

#pragma unroll
        for (int kk = 0; kk < BK; kk++) {
            float a[8], bv[4];
            float4 a0 = *(const float4*)&As[kk][ty * 8];
            float4 a1 = *(const float4*)&As[kk][ty * 8 + 4];
            a[0] = a0.x; a[1] = a0.y; a[2] = a0.z; a[3] = a0.w;
            a[4] = a1.x; a[5] = a1.y; a[6] = a1.z; a[7] = a1.w;
            float4 bb = *(const float4*)&Ws[kk][tx * 4];
            bv[0] = bb.x; bv[1] = bb.y; bv[2] = bb.z; bv[3] = bb.w;
#pragma unroll
            for (int i = 0; i < 8; i++)
#pragma unroll
                for (int j = 0; j < 4; j++)
                    acc[i][j] += a[i] * bv[j];
        }
        __syncthreads();
    }

#pragma unroll
    for (int i = 0; i < 8; i++) {
        int m = m0 + ty * 8 + i;
#pragma unroll
        for (int j = 0; j < 4; j++) {
            int n = n0 + tx * 4 + j;
            if (LAYOUT == 0) {
                C[(size_t)m * DMODEL + n] = acc[i][j];
            } else {
                // (B,H,T,dh): b = m>>11, t = m&2047, h = n>>6, d = n&63
                size_t idx = ((((size_t)(m >> 11) * NHEADS + (n >> 6)) * TSEQ
                               + (size_t)(m & (TSEQ - 1))) * DH) + (n & (DH - 1));
                C[idx] = acc[i][j];
            }
        }
    }
}

// ---------------------------------------------------------------------------
// Banded FlashAttention with adaptive-span soft mask.
// One block per (b*H+h, q-tile of 64). 256 threads (16x16), 4x4 micro-tiles.
// Online softmax; key loop restricted to the span window.
// ---------------------------------------------------------------------------
#define SROW 65                     // padded row stride (floats)
#define ATT_SMEM (4 * 64 * SROW * 4)

__global__ __launch_bounds__(256) void attn_kernel(const float* __restrict__ spans)
{
    extern __shared__ float sm[];
    float* Qs = sm;                   // [64][65]
    float* Ks = sm + 64 * SROW;
    float* Vs = sm + 2 * 64 * SROW;
    float* Ps = sm + 3 * 64 * SROW;

    const int tid = threadIdx.x;
    const int tx = tid & 15;
    const int ty = tid >> 4;
    const int bh = blockIdx.y;          // b*H + h
    const int h  = bh & (NHEADS - 1);
    const int b  = bh >> 3;
    const int qt = blockIdx.x;
    const int q0 = qt << 6;

    const float sp  = fminf(fmaxf(spans[h], 0.0f), 1.0f);
    const float eff = sp * 512.0f;
    const int dist_max = (int)floorf(eff) + 1;
    const int kt0 = max(0, q0 - dist_max) >> 6;

    const float* Qg = g_Q + ((size_t)bh * TSEQ + q0) * DH;
    const float* Kg = g_K + (size_t)bh * TSEQ * DH;
    const float* Vg = g_V + (size_t)bh * TSEQ * DH;

    // Load Q tile (contiguous 4096 floats)
#pragma unroll
    for (int it = 0; it < 4; it++) {
        int f = tid + it * 256;
        int r = f >> 4, dq = (f & 15) << 2;
        float4 v = ((const float4*)Qg)[f];
        Qs[r * SROW + dq + 0] = v.x;
        Qs[r * SROW + dq + 1] = v.y;
        Qs[r * SROW + dq + 2] = v.z;
        Qs[r * SROW + dq + 3] = v.w;
    }

    float mrow[4], lrow[4], o[4][4];
#pragma unroll
    for (int i = 0; i < 4; i++) {
        mrow[i] = -1e30f;
        lrow[i] = 0.0f;
#pragma unroll
        for (int j = 0; j < 4; j++) o[i][j] = 0.0f;
    }

    for (int kt = kt0; kt <= qt; kt++) {
        __syncthreads();   // previous O-loop done reading Ks/Vs/Ps
        const float4* K4 = (const float4*)(Kg + ((size_t)kt << 6) * DH);
        const float4* V4 = (const float4*)(Vg + ((size_t)kt << 6) * DH);
#pragma unroll
        for (int it = 0; it < 4; it++) {
            int f = tid + it * 256;
            int r = f >> 4, dq = (f & 15) << 2;
            float4 kv = K4[f];
            Ks[r * SROW + dq + 0] = kv.x;
            Ks[r * SROW + dq + 1] = kv.y;
            Ks[r * SROW + dq + 2] = kv.z;
            Ks[r * SROW + dq + 3] = kv.w;
            float4 vv = V4[f];
            Vs[r * SROW + dq + 0] = vv.x;
            Vs[r * SROW + dq + 1] = vv.y;
            Vs[r * SROW + dq + 2] = vv.z;
            Vs[r * SROW + dq + 3] = vv.w;
        }
        __syncthreads();

        // S = Q K^T (64x64 tile, each thread 4x4)
        float s[4][4];
#pragma unroll
        for (int i = 0; i < 4; i++)
#pragma unroll
            for (int j = 0; j < 4; j++) s[i][j] = 0.0f;

#pragma unroll 8
        for (int d = 0; d < 64; d++) {
            float qv[4], kv[4];
#pragma unroll
            for (int i = 0; i < 4; i++) qv[i] = Qs[(ty * 4 + i) * SROW + d];
#pragma unroll
            for (int j = 0; j < 4; j++) kv[j] = Ks[(tx * 4 + j) * SROW + d];
#pragma unroll
            for (int i = 0; i < 4; i++)
#pragma unroll
                for (int j = 0; j < 4; j++)
                    s[i][j] += qv[i] * kv[j];
        }

        // scale + adaptive-span mask + row max
        float mx[4];
#pragma unroll
        for (int i = 0; i < 4; i++) {
            float qgf = (float)(q0 + ty * 4 + i);
            float rowm = -1e30f;
#pragma unroll
            for (int j = 0; j < 4; j++) {
                float jjf = (float)((kt << 6) + tx * 4 + j);
                float dist = qgf - jjf;
                float R = (eff - dist + 1.0f) * 0.25f;
                float val;
                if (dist < 0.0f || R <= 0.0f)      val = NEG_INF_F;
                else if (R >= 1.0f)                val = 0.0f;   // log(1+1e-10) == 0 in fp32
                else                               val = __logf(R + 1e-10f);
                s[i][j] = s[i][j] * ATT_SCALE + val;
                rowm = fmaxf(rowm, s[i][j]);
            }
            rowm = fmaxf(rowm, __shfl_xor_sync(0xffffffffu, rowm, 1));
            rowm = fmaxf(rowm, __shfl_xor_sync(0xffffffffu, rowm, 2));
            rowm = fmaxf(rowm, __shfl_xor_sync(0xffffffffu, rowm, 4));
            rowm = fmaxf(rowm, __shfl_xor_sync(0xffffffffu, rowm, 8));
            mx[i] = rowm;
        }

        // online softmax update; stage P in shared
#pragma unroll
        for (int i = 0; i < 4; i++) {
            float mn = fmaxf(mrow[i], mx[i]);
            float corr = __expf(mrow[i] - mn);
            mrow[i] = mn;
            float rs = 0.0f;
#pragma unroll
            for (int j = 0; j < 4; j++) {
                float p = __expf(s[i][j] - mn);
                rs += p;
                Ps[(ty * 4 + i) * SROW + tx * 4 + j] = p;
            }
            rs += __shfl_xor_sync(0xffffffffu, rs, 1);
            rs += __shfl_xor_sync(0xffffffffu, rs, 2);
            rs += __shfl_xor_sync(0xffffffffu, rs, 4);
            rs += __shfl_xor_sync(0xffffffffu, rs, 8);
            lrow[i] = lrow[i] * corr + rs;
#pragma unroll
            for (int j = 0; j < 4; j++) o[i][j] *= corr;
        }
        __syncthreads();

        // O += P @ V
#pragma unroll 8
        for (int c = 0; c < 64; c++) {
            float pv[4], vv[4];
#pragma unroll
            for (int i = 0; i < 4; i++) pv[i] = Ps[(ty * 4 + i) * SROW + c];
#pragma unroll
            for (int j = 0; j < 4; j++) vv[j] = Vs[c * SROW + tx * 4 + j];
#pragma unroll
            for (int i = 0; i < 4; i++)
#pragma unroll
                for (int j = 0; j < 4; j++)
                    o[i][j] += pv[i] * vv[j];
        }
    }

    // normalize + write to (B*T, D) layout for the output projection
#pragma unroll
    for (int i = 0; i < 4; i++) {
        float inv = 1.0f / lrow[i];
        int q = q0 + ty * 4 + i;
        size_t base = ((size_t)(b * TSEQ + q)) * DMODEL + h * DH + tx * 4;
#pragma unroll
        for (int j = 0; j < 4; j++)
            g_AO[base + j] = o[i][j] * inv;
    }
}

// ---------------------------------------------------------------------------
__global__ void span_loss_kernel(const float* __restrict__ spans,
                                 float* __restrict__ out, int off)
{
    if (threadIdx.x == 0) {
        float sum = 0.0f;
        for (int i = 0; i < NHEADS; i++)
            sum += fminf(fmaxf(spans[i], 0.0f), 1.0f);
        out[off] = 2e-4f * (sum / (float)NHEADS);
    }
}

// ---------------------------------------------------------------------------
extern "C" void kernel_launch(void* const* d_in, const int* in_sizes, int n_in,
                              void* d_out, int out_size)
{
    const float* x  = (const float*)d_in[0];
    const float* wq = (const float*)d_in[1];
    const float* wk = (const float*)d_in[2];
    const float* wv = (const float*)d_in[3];
    const float* wo = (const float*)d_in[4];
    const float* sp = (const float*)d_in[5];

    const int M = in_sizes[0] / DMODEL;   // B*T
    const int B = M / TSEQ;

    float *pQ, *pK, *pV, *pAO;
    cudaGetSymbolAddress((void**)&pQ,  g_Q);
    cudaGetSymbolAddress((void**)&pK,  g_K);
    cudaGetSymbolAddress((void**)&pV,  g_V);
    cudaGetSymbolAddress((void**)&pAO, g_AO);

    dim3 gg(DMODEL / BN, M / BM);
    gemm_kernel<1><<<gg, 256>>>(x, wq, pQ, M);
    gemm_kernel<1><<<gg, 256>>>(x, wk, pK, M);
    gemm_kernel<1><<<gg, 256>>>(x, wv, pV, M);

    cudaFuncSetAttribute(attn_kernel,
                         cudaFuncAttributeMaxDynamicSharedMemorySize, ATT_SMEM);
    attn_kernel<<<dim3(TSEQ / 64, B * NHEADS), 256, ATT_SMEM>>>(sp);

    gemm_kernel<0><<<gg, 256>>>(pAO, wo, (float*)d_out, M);

    if (out_size > M * DMODEL)
        span_loss_kernel<<<1, 32>>>(sp, (float*)d_out, M * DMODEL);
}